// round 4
// baseline (speedup 1.0000x reference)
#include <cuda_runtime.h>
#include <math.h>
#include <stdint.h>

#define NNODES 50000
#define EEDGES 800000
#define ETOT   (EEDGES + NNODES)
#define DHID   128
#define DFEAT  256          // HEADS * HID
#define NEG_SLOPE 0.2f
#define EPSV 1e-16f

// ---------------- scratch (no allocation allowed) ----------------
__device__ float g_h1[NNODES * DFEAT];
__device__ float g_agg1[NNODES * DFEAT];
__device__ float g_h2[NNODES * DFEAT];
__device__ float g_agg2[NNODES * DFEAT];
__device__ float g_asad[NNODES * 4];   // [0,2N): alpha_src ; [2N,4N): alpha_dst
__device__ float g_wc[DFEAT + 1];
__device__ int   g_cnt[NNODES];
__device__ int   g_rowptr[NNODES];
__device__ int   g_cursor[NNODES];
__device__ int   g_colidx[ETOT];
__device__ int   g_bsum[256];

// ================= utility zero kernels =================
__global__ void zero2_kernel(int* a, int na, float* b, int nb) {
    int i = blockIdx.x * blockDim.x + threadIdx.x;
    if (i < na) a[i] = 0;
    if (i < nb) b[i] = 0.f;
}
__global__ void zero_f_kernel(float* p, int n) {
    int i = blockIdx.x * blockDim.x + threadIdx.x;
    if (i < n) p[i] = 0.f;
}

// ================= CSR construction =================
__global__ void count_kernel(const int* __restrict__ ei, int* __restrict__ cnt,
                             int E, int Etot) {
    int t = blockIdx.x * blockDim.x + threadIdx.x;
    if (t >= Etot) return;
    int d = (t < E) ? ei[E + t] : (t - E);
    atomicAdd(&cnt[d], 1);
}

__global__ void scan_block_sums(const int* __restrict__ cnt, int* __restrict__ bsum, int N) {
    __shared__ int sh[256];
    int tid = threadIdx.x;
    int i = blockIdx.x * 256 + tid;
    sh[tid] = (i < N) ? cnt[i] : 0;
    __syncthreads();
    for (int s = 128; s > 0; s >>= 1) {
        if (tid < s) sh[tid] += sh[tid + s];
        __syncthreads();
    }
    if (tid == 0) bsum[blockIdx.x] = sh[0];
}

__global__ void scan_bsums(int* bsum, int nb) {
    __shared__ int sh[256];
    int tid = threadIdx.x;
    int v0 = (tid < nb) ? bsum[tid] : 0;
    sh[tid] = v0;
    __syncthreads();
    for (int off = 1; off < 256; off <<= 1) {
        int v = (tid >= off) ? sh[tid - off] : 0;
        __syncthreads();
        sh[tid] += v;
        __syncthreads();
    }
    if (tid < nb) bsum[tid] = sh[tid] - v0;   // exclusive
}

__global__ void scan_final(const int* __restrict__ cnt, const int* __restrict__ bsum,
                           int* __restrict__ rowptr, int* __restrict__ cursor, int N) {
    __shared__ int sh[256];
    int tid = threadIdx.x;
    int i = blockIdx.x * 256 + tid;
    int v0 = (i < N) ? cnt[i] : 0;
    sh[tid] = v0;
    __syncthreads();
    for (int off = 1; off < 256; off <<= 1) {
        int v = (tid >= off) ? sh[tid - off] : 0;
        __syncthreads();
        sh[tid] += v;
        __syncthreads();
    }
    if (i < N) {
        int excl = sh[tid] - v0 + bsum[blockIdx.x];
        rowptr[i] = excl;
        cursor[i] = excl;
    }
}

__global__ void scatter_kernel(const int* __restrict__ ei, int* __restrict__ cursor,
                               int* __restrict__ colidx, int E, int Etot) {
    int t = blockIdx.x * blockDim.x + threadIdx.x;
    if (t >= Etot) return;
    int s, d;
    if (t < E) { s = ei[t]; d = ei[E + t]; } else { s = d = t - E; }
    int pos = atomicAdd(&cursor[d], 1);
    colidx[pos] = s;
}

// ================= 3xTF32 tensor-core GEMM, double-buffered, fused alpha =================
__device__ __forceinline__ uint32_t f2tf32(float f) {
    uint32_t u;
    asm("cvt.rna.tf32.f32 %0, %1;" : "=r"(u) : "f"(f));
    return u;
}

__device__ __forceinline__ void mma_tf32(float* c, const uint32_t* a, const uint32_t* b) {
    asm volatile(
        "mma.sync.aligned.m16n8k8.row.col.f32.tf32.tf32.f32 "
        "{%0,%1,%2,%3}, {%4,%5,%6,%7}, {%8,%9}, {%0,%1,%2,%3};"
        : "+f"(c[0]), "+f"(c[1]), "+f"(c[2]), "+f"(c[3])
        : "r"(a[0]), "r"(a[1]), "r"(a[2]), "r"(a[3]), "r"(b[0]), "r"(b[1]));
}

// stage layout (words): A_hi 128*20 | A_lo 128*20 | B_hi 16*72 | B_lo 16*72 = 7424
#define STG_W 7424
#define AHs(st,r,c) sm_[(st)*STG_W + (r)*20 + (c)]
#define ALs(st,r,c) sm_[(st)*STG_W + 2560 + (r)*20 + (c)]
#define BHs(st,r,c) sm_[(st)*STG_W + 5120 + (r)*72 + (c)]
#define BLs(st,r,c) sm_[(st)*STG_W + 6272 + (r)*72 + (c)]

template <int FUSE_RELU>
__global__ void __launch_bounds__(256) gemm_tf32_kernel(
    const float* __restrict__ A, const float* __restrict__ B,
    const float* __restrict__ bias, float* __restrict__ C,
    const float* __restrict__ a_src, const float* __restrict__ a_dst,
    float* __restrict__ asad,
    int M, int N, int K, int Nn)
{
    extern __shared__ uint32_t sm_[];
    const int tid  = threadIdx.x;
    const int lane = tid & 31;
    const int warp = tid >> 5;
    const int wm   = warp & 3;
    const int wn   = warp >> 2;
    const int gid  = lane >> 2;
    const int tig  = lane & 3;
    const int m0 = blockIdx.x * 128;
    const int n0 = blockIdx.y * 64;

    const int arow = tid >> 2, ac4 = tid & 3;     // A tile: rows arow, arow+64
    const int brow = tid >> 4, bc4 = tid & 15;    // B tile

    float c_[2][4][4];
#pragma unroll
    for (int fm = 0; fm < 2; fm++)
#pragma unroll
        for (int fn = 0; fn < 4; fn++)
#pragma unroll
            for (int j = 0; j < 4; j++) c_[fm][fn][j] = 0.f;

    auto ldA = [&](int k0, int row) -> float4 {
        int gm = m0 + row;
        float4 f = make_float4(0.f, 0.f, 0.f, 0.f);
        if (gm < M) f = *(const float4*)&A[(size_t)gm * K + k0 + ac4 * 4];
        if (FUSE_RELU) {
            float4 bb = *(const float4*)&bias[k0 + ac4 * 4];
            f.x = fmaxf(f.x + bb.x, 0.f);
            f.y = fmaxf(f.y + bb.y, 0.f);
            f.z = fmaxf(f.z + bb.z, 0.f);
            f.w = fmaxf(f.w + bb.w, 0.f);
        }
        return f;
    };
    auto stA = [&](int st, int row, float4 f) {
        uint32_t h0 = f2tf32(f.x), h1 = f2tf32(f.y), h2 = f2tf32(f.z), h3 = f2tf32(f.w);
        uint32_t l0 = f2tf32(f.x - __uint_as_float(h0));
        uint32_t l1 = f2tf32(f.y - __uint_as_float(h1));
        uint32_t l2 = f2tf32(f.z - __uint_as_float(h2));
        uint32_t l3 = f2tf32(f.w - __uint_as_float(h3));
        *(uint4*)&AHs(st, row, ac4 * 4) = make_uint4(h0, h1, h2, h3);
        *(uint4*)&ALs(st, row, ac4 * 4) = make_uint4(l0, l1, l2, l3);
    };
    auto stB = [&](int st, float4 f) {
        uint32_t h0 = f2tf32(f.x), h1 = f2tf32(f.y), h2 = f2tf32(f.z), h3 = f2tf32(f.w);
        uint32_t l0 = f2tf32(f.x - __uint_as_float(h0));
        uint32_t l1 = f2tf32(f.y - __uint_as_float(h1));
        uint32_t l2 = f2tf32(f.z - __uint_as_float(h2));
        uint32_t l3 = f2tf32(f.w - __uint_as_float(h3));
        *(uint4*)&BHs(st, brow, bc4 * 4) = make_uint4(h0, h1, h2, h3);
        *(uint4*)&BLs(st, brow, bc4 * 4) = make_uint4(l0, l1, l2, l3);
    };

    // prologue: fill stage 0
    stA(0, arow,      ldA(0, arow));
    stA(0, arow + 64, ldA(0, arow + 64));
    stB(0, *(const float4*)&B[(size_t)brow * N + n0 + bc4 * 4]);
    __syncthreads();

    int p = 0;
    for (int k0 = 0; k0 < K; k0 += 16) {
        const bool hn = (k0 + 16) < K;
        float4 nA0, nA1, nB;
        if (hn) {
            nA0 = ldA(k0 + 16, arow);
            nA1 = ldA(k0 + 16, arow + 64);
            nB = *(const float4*)&B[(size_t)(k0 + 16 + brow) * N + n0 + bc4 * 4];
        }
        // MMA on stage p
#pragma unroll
        for (int kk = 0; kk < 2; kk++) {
            uint32_t ah[2][4], al[2][4], bh[4][2], bl[4][2];
#pragma unroll
            for (int fm = 0; fm < 2; fm++) {
                int r = wm * 32 + fm * 16;
                int cA = kk * 8 + tig;
                ah[fm][0] = AHs(p, r + gid, cA);          al[fm][0] = ALs(p, r + gid, cA);
                ah[fm][1] = AHs(p, r + gid + 8, cA);      al[fm][1] = ALs(p, r + gid + 8, cA);
                ah[fm][2] = AHs(p, r + gid, cA + 4);      al[fm][2] = ALs(p, r + gid, cA + 4);
                ah[fm][3] = AHs(p, r + gid + 8, cA + 4);  al[fm][3] = ALs(p, r + gid + 8, cA + 4);
            }
#pragma unroll
            for (int fn = 0; fn < 4; fn++) {
                int cc = wn * 32 + fn * 8 + gid;
                bh[fn][0] = BHs(p, kk * 8 + tig, cc);      bl[fn][0] = BLs(p, kk * 8 + tig, cc);
                bh[fn][1] = BHs(p, kk * 8 + tig + 4, cc);  bl[fn][1] = BLs(p, kk * 8 + tig + 4, cc);
            }
#pragma unroll
            for (int fm = 0; fm < 2; fm++)
#pragma unroll
                for (int fn = 0; fn < 4; fn++) {
                    mma_tf32(c_[fm][fn], ah[fm], bh[fn]);   // hi*hi
                    mma_tf32(c_[fm][fn], ah[fm], bl[fn]);   // hi*lo
                    mma_tf32(c_[fm][fn], al[fm], bh[fn]);   // lo*hi
                }
        }
        if (hn) {
            stA(p ^ 1, arow,      nA0);
            stA(p ^ 1, arow + 64, nA1);
            stB(p ^ 1, nB);
            __syncthreads();
            p ^= 1;
        }
    }

    // ---- epilogue: store C + fused alpha partials ----
    const int head = (n0 + wn * 32) >> 7;
#pragma unroll
    for (int fm = 0; fm < 2; fm++) {
        float s1 = 0.f, s2 = 0.f, d1 = 0.f, d2 = 0.f;
        int gm1 = m0 + wm * 32 + fm * 16 + gid;
        int gm2 = gm1 + 8;
#pragma unroll
        for (int fn = 0; fn < 4; fn++) {
            int gn = n0 + wn * 32 + fn * 8 + 2 * tig;
            float a0 = __ldg(&a_src[gn]), a1 = __ldg(&a_src[gn + 1]);
            float q0 = __ldg(&a_dst[gn]), q1 = __ldg(&a_dst[gn + 1]);
            s1 += c_[fm][fn][0] * a0 + c_[fm][fn][1] * a1;
            s2 += c_[fm][fn][2] * a0 + c_[fm][fn][3] * a1;
            d1 += c_[fm][fn][0] * q0 + c_[fm][fn][1] * q1;
            d2 += c_[fm][fn][2] * q0 + c_[fm][fn][3] * q1;
            if (gm1 < M)
                *(float2*)&C[(size_t)gm1 * N + gn] = make_float2(c_[fm][fn][0], c_[fm][fn][1]);
            if (gm2 < M)
                *(float2*)&C[(size_t)gm2 * N + gn] = make_float2(c_[fm][fn][2], c_[fm][fn][3]);
        }
        // reduce over the 4 lanes of each quad (same gid, tig=0..3)
        s1 += __shfl_xor_sync(0xffffffffu, s1, 1); s1 += __shfl_xor_sync(0xffffffffu, s1, 2);
        s2 += __shfl_xor_sync(0xffffffffu, s2, 1); s2 += __shfl_xor_sync(0xffffffffu, s2, 2);
        d1 += __shfl_xor_sync(0xffffffffu, d1, 1); d1 += __shfl_xor_sync(0xffffffffu, d1, 2);
        d2 += __shfl_xor_sync(0xffffffffu, d2, 1); d2 += __shfl_xor_sync(0xffffffffu, d2, 2);
        if (tig == 0) {
            if (gm1 < M) {
                atomicAdd(&asad[gm1 * 2 + head], s1);
                atomicAdd(&asad[2 * Nn + gm1 * 2 + head], d1);
            }
            if (gm2 < M) {
                atomicAdd(&asad[gm2 * 2 + head], s2);
                atomicAdd(&asad[2 * Nn + gm2 * 2 + head], d2);
            }
        }
    }
}

// ================= fused CSR softmax-aggregation =================
// One warp per (dst node, head); atomic-free single pass.
__global__ void agg_csr_kernel(const int* __restrict__ rowptr, const int* __restrict__ cnt,
                               const int* __restrict__ colidx,
                               const float* __restrict__ h,
                               const float* __restrict__ asad,
                               float* __restrict__ out, int N)
{
    int gw = (blockIdx.x * blockDim.x + threadIdx.x) >> 5;
    int lane = threadIdx.x & 31;
    if (gw >= N * 2) return;
    int node = gw >> 1, head = gw & 1;
    int start = rowptr[node];
    int deg   = cnt[node];
    float adv = asad[2 * N + node * 2 + head];
    const float4* h4 = (const float4*)h + head * 32 + lane;

    float4 acc = make_float4(0.f, 0.f, 0.f, 0.f);
    float den = 0.f;

    int s = __ldg(&colidx[start]);   // deg >= 1 always (self loop)
    for (int i = 0; i < deg; i++) {
        int scur = s;
        if (i + 1 < deg) s = __ldg(&colidx[start + i + 1]);
        float e = __ldg(&asad[scur * 2 + head]) + adv;
        e = e > 0.f ? e : NEG_SLOPE * e;
        float w = __expf(e);
        float4 v = h4[(size_t)scur * 64];
        den += w;
        acc.x = fmaf(w, v.x, acc.x);
        acc.y = fmaf(w, v.y, acc.y);
        acc.z = fmaf(w, v.z, acc.z);
        acc.w = fmaf(w, v.w, acc.w);
    }
    float r = 1.f / (den + EPSV);
    ((float4*)out)[(size_t)node * 64 + head * 32 + lane] =
        make_float4(acc.x * r, acc.y * r, acc.z * r, acc.w * r);
}

// ================= collapsed post-MLP =================
__global__ void wc_kernel(const float* __restrict__ Wp1, const float* __restrict__ bp1,
                          const float* __restrict__ Wp2, const float* __restrict__ bp2,
                          float* __restrict__ wc)
{
    int i = threadIdx.x;  // 256 threads
    float acc = 0.f;
    for (int j = 0; j < DHID; j++) acc += Wp1[i * DHID + j] * Wp2[j];
    wc[i] = acc;
    if (i == 0) {
        float b = 0.f;
        for (int j = 0; j < DHID; j++) b += bp1[j] * Wp2[j];
        wc[DFEAT] = b + bp2[0];
    }
}

__global__ void final_kernel(const float* __restrict__ agg2,
                             const float* __restrict__ b2,
                             const float* __restrict__ wc,
                             float* __restrict__ out, int N)
{
    int gw = (blockIdx.x * blockDim.x + threadIdx.x) >> 5;
    int lane = threadIdx.x & 31;
    if (gw >= N) return;
    const float* hp = agg2 + (size_t)gw * DFEAT;
    float acc = 0.f;
#pragma unroll
    for (int r = 0; r < 2; r++) {
        int cidx = r * 128 + lane * 4;
        float4 v  = *(const float4*)&hp[cidx];
        float4 bb = *(const float4*)&b2[cidx];
        float4 ww = *(const float4*)&wc[cidx];
        acc += fmaxf(v.x + bb.x, 0.f) * ww.x;
        acc += fmaxf(v.y + bb.y, 0.f) * ww.y;
        acc += fmaxf(v.z + bb.z, 0.f) * ww.z;
        acc += fmaxf(v.w + bb.w, 0.f) * ww.w;
    }
#pragma unroll
    for (int o = 16; o; o >>= 1) acc += __shfl_xor_sync(0xffffffffu, acc, o);
    if (lane == 0) {
        float z = acc + wc[DFEAT];
        out[gw] = 1.f / (1.f + expf(-z));
    }
}

// ================= launch =================
extern "C" void kernel_launch(void* const* d_in, const int* in_sizes, int n_in,
                              void* d_out, int out_size)
{
    const float* x      = (const float*)d_in[0];
    const int*   ei     = (const int*)  d_in[1];
    const float* W1     = (const float*)d_in[2];
    const float* a_src1 = (const float*)d_in[3];
    const float* a_dst1 = (const float*)d_in[4];
    const float* b1     = (const float*)d_in[5];
    const float* W2     = (const float*)d_in[6];
    const float* a_src2 = (const float*)d_in[7];
    const float* a_dst2 = (const float*)d_in[8];
    const float* b2     = (const float*)d_in[9];
    const float* Wp1    = (const float*)d_in[10];
    const float* bp1    = (const float*)d_in[11];
    const float* Wp2    = (const float*)d_in[12];
    const float* bp2    = (const float*)d_in[13];

    const int N = in_sizes[0] / 128;
    const int E = in_sizes[1] / 2;
    const int Etot = E + N;

    float *h1, *agg1, *h2, *agg2, *asad, *wc;
    int *cnt, *rowptr, *cursor, *colidx, *bsum;
    cudaGetSymbolAddress((void**)&h1,   g_h1);
    cudaGetSymbolAddress((void**)&agg1, g_agg1);
    cudaGetSymbolAddress((void**)&h2,   g_h2);
    cudaGetSymbolAddress((void**)&agg2, g_agg2);
    cudaGetSymbolAddress((void**)&asad, g_asad);
    cudaGetSymbolAddress((void**)&wc,   g_wc);
    cudaGetSymbolAddress((void**)&cnt,    g_cnt);
    cudaGetSymbolAddress((void**)&rowptr, g_rowptr);
    cudaGetSymbolAddress((void**)&cursor, g_cursor);
    cudaGetSymbolAddress((void**)&colidx, g_colidx);
    cudaGetSymbolAddress((void**)&bsum,   g_bsum);

    const int smem_bytes = 2 * STG_W * 4;   // 59392
    cudaFuncSetAttribute(gemm_tf32_kernel<0>, cudaFuncAttributeMaxDynamicSharedMemorySize, smem_bytes);
    cudaFuncSetAttribute(gemm_tf32_kernel<1>, cudaFuncAttributeMaxDynamicSharedMemorySize, smem_bytes);

    const int nb = (N + 255) / 256;
    dim3 gemm_grid((N + 127) / 128, DFEAT / 64);
    const int agg_blocks   = (N * 2 * 32 + 255) / 256;
    const int final_blocks = (N * 32 + 255) / 256;
    const int edge_blocks  = (Etot + 255) / 256;
    const int z2_blocks    = (4 * N + 255) / 256;

    // 1-3: CSR start + zero (asad zeroed for gemm1's fused alpha)
    zero2_kernel<<<z2_blocks, 256>>>(cnt, N, asad, 4 * N);
    count_kernel<<<edge_blocks, 256>>>(ei, cnt, E, Etot);
    scan_block_sums<<<nb, 256>>>(cnt, bsum, N);
    // 4: gemm1 (slot 4 -> profiled by ncu next round)
    gemm_tf32_kernel<0><<<gemm_grid, 256, smem_bytes>>>(
        x, W1, nullptr, h1, a_src1, a_dst1, asad, N, DFEAT, 128, N);
    // 5-7: finish CSR
    scan_bsums<<<1, 256>>>(bsum, nb);
    scan_final<<<nb, 256>>>(cnt, bsum, rowptr, cursor, N);
    scatter_kernel<<<edge_blocks, 256>>>(ei, cursor, colidx, E, Etot);
    // 8: layer-1 aggregation
    agg_csr_kernel<<<agg_blocks, 256>>>(rowptr, cnt, colidx, h1, asad, agg1, N);
    // 9-11: layer 2
    zero_f_kernel<<<z2_blocks, 256>>>(asad, 4 * N);
    gemm_tf32_kernel<1><<<gemm_grid, 256, smem_bytes>>>(
        agg1, W2, b1, h2, a_src2, a_dst2, asad, N, DFEAT, DFEAT, N);
    agg_csr_kernel<<<agg_blocks, 256>>>(rowptr, cnt, colidx, h2, asad, agg2, N);
    // 12-13: collapsed post-MLP + sigmoid
    wc_kernel<<<1, 256>>>(Wp1, bp1, Wp2, bp2, wc);
    final_kernel<<<final_blocks, 256>>>(agg2, b2, wc, (float*)d_out, N);
}

// round 5
// speedup vs baseline: 1.0295x; 1.0295x over previous
#include <cuda_runtime.h>
#include <math.h>
#include <stdint.h>

#define NNODES 50000
#define EEDGES 800000
#define ETOT   (EEDGES + NNODES)
#define DHID   128
#define DFEAT  256          // HEADS * HID
#define NEG_SLOPE 0.2f
#define EPSV 1e-16f

// ---------------- scratch (no allocation allowed) ----------------
__device__ float g_h1[NNODES * DFEAT];
__device__ float g_agg1[NNODES * DFEAT];
__device__ float g_h2[NNODES * DFEAT];
__device__ float g_agg2[NNODES * DFEAT];
__device__ float g_asad[NNODES * 4];   // [0,2N): alpha_src ; [2N,4N): alpha_dst
__device__ float g_wc[DFEAT + 1];
__device__ int   g_cnt[NNODES];
__device__ int   g_rowptr[NNODES];
__device__ int   g_cursor[NNODES];
__device__ int   g_colidx[ETOT];
__device__ int   g_bsum[256];

// ================= utility zero kernels =================
__global__ void zero2_kernel(int* a, int na, float* b, int nb) {
    int i = blockIdx.x * blockDim.x + threadIdx.x;
    if (i < na) a[i] = 0;
    if (i < nb) b[i] = 0.f;
}
__global__ void zero_f_kernel(float* p, int n) {
    int i = blockIdx.x * blockDim.x + threadIdx.x;
    if (i < n) p[i] = 0.f;
}

// ================= CSR construction =================
__global__ void count_kernel(const int* __restrict__ ei, int* __restrict__ cnt,
                             int E, int Etot) {
    int t = blockIdx.x * blockDim.x + threadIdx.x;
    if (t >= Etot) return;
    int d = (t < E) ? ei[E + t] : (t - E);
    atomicAdd(&cnt[d], 1);
}

__global__ void scan_block_sums(const int* __restrict__ cnt, int* __restrict__ bsum, int N) {
    __shared__ int sh[256];
    int tid = threadIdx.x;
    int i = blockIdx.x * 256 + tid;
    sh[tid] = (i < N) ? cnt[i] : 0;
    __syncthreads();
    for (int s = 128; s > 0; s >>= 1) {
        if (tid < s) sh[tid] += sh[tid + s];
        __syncthreads();
    }
    if (tid == 0) bsum[blockIdx.x] = sh[0];
}

__global__ void scan_bsums(int* bsum, int nb) {
    __shared__ int sh[256];
    int tid = threadIdx.x;
    int v0 = (tid < nb) ? bsum[tid] : 0;
    sh[tid] = v0;
    __syncthreads();
    for (int off = 1; off < 256; off <<= 1) {
        int v = (tid >= off) ? sh[tid - off] : 0;
        __syncthreads();
        sh[tid] += v;
        __syncthreads();
    }
    if (tid < nb) bsum[tid] = sh[tid] - v0;   // exclusive
}

__global__ void scan_final(const int* __restrict__ cnt, const int* __restrict__ bsum,
                           int* __restrict__ rowptr, int* __restrict__ cursor, int N) {
    __shared__ int sh[256];
    int tid = threadIdx.x;
    int i = blockIdx.x * 256 + tid;
    int v0 = (i < N) ? cnt[i] : 0;
    sh[tid] = v0;
    __syncthreads();
    for (int off = 1; off < 256; off <<= 1) {
        int v = (tid >= off) ? sh[tid - off] : 0;
        __syncthreads();
        sh[tid] += v;
        __syncthreads();
    }
    if (i < N) {
        int excl = sh[tid] - v0 + bsum[blockIdx.x];
        rowptr[i] = excl;
        cursor[i] = excl;
    }
}

__global__ void scatter_kernel(const int* __restrict__ ei, int* __restrict__ cursor,
                               int* __restrict__ colidx, int E, int Etot) {
    int t = blockIdx.x * blockDim.x + threadIdx.x;
    if (t >= Etot) return;
    int s, d;
    if (t < E) { s = ei[t]; d = ei[E + t]; } else { s = d = t - E; }
    int pos = atomicAdd(&cursor[d], 1);
    colidx[pos] = s;
}

// ================= 3xTF32 tensor-core GEMM (single buffer) + fused alpha =================
__device__ __forceinline__ uint32_t f2tf32(float f) {
    uint32_t u;
    asm("cvt.rna.tf32.f32 %0, %1;" : "=r"(u) : "f"(f));
    return u;
}

__device__ __forceinline__ void mma_tf32(float* c, const uint32_t* a, const uint32_t* b) {
    asm volatile(
        "mma.sync.aligned.m16n8k8.row.col.f32.tf32.tf32.f32 "
        "{%0,%1,%2,%3}, {%4,%5,%6,%7}, {%8,%9}, {%0,%1,%2,%3};"
        : "+f"(c[0]), "+f"(c[1]), "+f"(c[2]), "+f"(c[3])
        : "r"(a[0]), "r"(a[1]), "r"(a[2]), "r"(a[3]), "r"(b[0]), "r"(b[1]));
}

template <int FUSE_RELU>
__global__ void __launch_bounds__(256) gemm_tf32_kernel(
    const float* __restrict__ A, const float* __restrict__ B,
    const float* __restrict__ bias, float* __restrict__ C,
    const float* __restrict__ a_src, const float* __restrict__ a_dst,
    float* __restrict__ asad,
    int M, int N, int K, int Nn)
{
    __shared__ uint32_t Ah[128][20];   // pad 4: frag bank = 4*gid+tig (bijective)
    __shared__ uint32_t Al[128][20];
    __shared__ uint32_t Bh[16][72];    // pad 8: frag bank = 8*tig+gid (bijective)
    __shared__ uint32_t Bl[16][72];

    const int tid  = threadIdx.x;
    const int lane = tid & 31;
    const int warp = tid >> 5;
    const int wm   = warp & 3;     // m warp: wm*32
    const int wn   = warp >> 2;    // n warp: wn*32
    const int gid  = lane >> 2;
    const int tig  = lane & 3;
    const int m0 = blockIdx.x * 128;
    const int n0 = blockIdx.y * 64;

    float c_[2][4][4];
#pragma unroll
    for (int fm = 0; fm < 2; fm++)
#pragma unroll
        for (int fn = 0; fn < 4; fn++)
#pragma unroll
            for (int j = 0; j < 4; j++) c_[fm][fn][j] = 0.f;

    for (int k0 = 0; k0 < K; k0 += 16) {
        // ---- load A tile (128x16): 512 float4, 2 per thread ----
#pragma unroll
        for (int it = 0; it < 2; it++) {
            int idx = tid + it * 256;
            int row = idx >> 2, c4 = idx & 3;
            int gm = m0 + row;
            float4 f = make_float4(0.f, 0.f, 0.f, 0.f);
            if (gm < M) f = *(const float4*)&A[(size_t)gm * K + k0 + c4 * 4];
            if (FUSE_RELU) {
                float4 bb = *(const float4*)&bias[k0 + c4 * 4];
                f.x = fmaxf(f.x + bb.x, 0.f);
                f.y = fmaxf(f.y + bb.y, 0.f);
                f.z = fmaxf(f.z + bb.z, 0.f);
                f.w = fmaxf(f.w + bb.w, 0.f);
            }
            uint32_t h0 = f2tf32(f.x), h1 = f2tf32(f.y), h2 = f2tf32(f.z), h3 = f2tf32(f.w);
            uint32_t l0 = f2tf32(f.x - __uint_as_float(h0));
            uint32_t l1 = f2tf32(f.y - __uint_as_float(h1));
            uint32_t l2 = f2tf32(f.z - __uint_as_float(h2));
            uint32_t l3 = f2tf32(f.w - __uint_as_float(h3));
            *(uint4*)&Ah[row][c4 * 4] = make_uint4(h0, h1, h2, h3);
            *(uint4*)&Al[row][c4 * 4] = make_uint4(l0, l1, l2, l3);
        }
        // ---- load B tile (16x64): 256 float4, 1 per thread ----
        {
            int row = tid >> 4, c4 = tid & 15;
            float4 f = *(const float4*)&B[(size_t)(k0 + row) * N + n0 + c4 * 4];
            uint32_t h0 = f2tf32(f.x), h1 = f2tf32(f.y), h2 = f2tf32(f.z), h3 = f2tf32(f.w);
            uint32_t l0 = f2tf32(f.x - __uint_as_float(h0));
            uint32_t l1 = f2tf32(f.y - __uint_as_float(h1));
            uint32_t l2 = f2tf32(f.z - __uint_as_float(h2));
            uint32_t l3 = f2tf32(f.w - __uint_as_float(h3));
            *(uint4*)&Bh[row][c4 * 4] = make_uint4(h0, h1, h2, h3);
            *(uint4*)&Bl[row][c4 * 4] = make_uint4(l0, l1, l2, l3);
        }
        __syncthreads();

#pragma unroll
        for (int kk = 0; kk < 2; kk++) {
            uint32_t ah[2][4], al[2][4], bh[4][2], bl[4][2];
#pragma unroll
            for (int fm = 0; fm < 2; fm++) {
                int r = wm * 32 + fm * 16;
                int cA = kk * 8 + tig;
                ah[fm][0] = Ah[r + gid][cA];         al[fm][0] = Al[r + gid][cA];
                ah[fm][1] = Ah[r + gid + 8][cA];     al[fm][1] = Al[r + gid + 8][cA];
                ah[fm][2] = Ah[r + gid][cA + 4];     al[fm][2] = Al[r + gid][cA + 4];
                ah[fm][3] = Ah[r + gid + 8][cA + 4]; al[fm][3] = Al[r + gid + 8][cA + 4];
            }
#pragma unroll
            for (int fn = 0; fn < 4; fn++) {
                int cc = wn * 32 + fn * 8 + gid;
                bh[fn][0] = Bh[kk * 8 + tig][cc];     bl[fn][0] = Bl[kk * 8 + tig][cc];
                bh[fn][1] = Bh[kk * 8 + tig + 4][cc]; bl[fn][1] = Bl[kk * 8 + tig + 4][cc];
            }
#pragma unroll
            for (int fm = 0; fm < 2; fm++)
#pragma unroll
                for (int fn = 0; fn < 4; fn++) {
                    mma_tf32(c_[fm][fn], ah[fm], bh[fn]);   // hi*hi
                    mma_tf32(c_[fm][fn], ah[fm], bl[fn]);   // hi*lo
                    mma_tf32(c_[fm][fn], al[fm], bh[fn]);   // lo*hi
                }
        }
        __syncthreads();
    }

    // ---- epilogue: store C + fused alpha partials ----
    const int head = (n0 + wn * 32) >> 7;
#pragma unroll
    for (int fm = 0; fm < 2; fm++) {
        float s1 = 0.f, s2 = 0.f, d1 = 0.f, d2 = 0.f;
        int gm1 = m0 + wm * 32 + fm * 16 + gid;
        int gm2 = gm1 + 8;
#pragma unroll
        for (int fn = 0; fn < 4; fn++) {
            int gn = n0 + wn * 32 + fn * 8 + 2 * tig;
            float a0 = __ldg(&a_src[gn]), a1 = __ldg(&a_src[gn + 1]);
            float q0 = __ldg(&a_dst[gn]), q1 = __ldg(&a_dst[gn + 1]);
            s1 += c_[fm][fn][0] * a0 + c_[fm][fn][1] * a1;
            s2 += c_[fm][fn][2] * a0 + c_[fm][fn][3] * a1;
            d1 += c_[fm][fn][0] * q0 + c_[fm][fn][1] * q1;
            d2 += c_[fm][fn][2] * q0 + c_[fm][fn][3] * q1;
            if (gm1 < M)
                *(float2*)&C[(size_t)gm1 * N + gn] = make_float2(c_[fm][fn][0], c_[fm][fn][1]);
            if (gm2 < M)
                *(float2*)&C[(size_t)gm2 * N + gn] = make_float2(c_[fm][fn][2], c_[fm][fn][3]);
        }
        // reduce over the 4 lanes of each quad (same gid, tig=0..3)
        s1 += __shfl_xor_sync(0xffffffffu, s1, 1); s1 += __shfl_xor_sync(0xffffffffu, s1, 2);
        s2 += __shfl_xor_sync(0xffffffffu, s2, 1); s2 += __shfl_xor_sync(0xffffffffu, s2, 2);
        d1 += __shfl_xor_sync(0xffffffffu, d1, 1); d1 += __shfl_xor_sync(0xffffffffu, d1, 2);
        d2 += __shfl_xor_sync(0xffffffffu, d2, 1); d2 += __shfl_xor_sync(0xffffffffu, d2, 2);
        if (tig == 0) {
            if (gm1 < M) {
                atomicAdd(&asad[gm1 * 2 + head], s1);
                atomicAdd(&asad[2 * Nn + gm1 * 2 + head], d1);
            }
            if (gm2 < M) {
                atomicAdd(&asad[gm2 * 2 + head], s2);
                atomicAdd(&asad[2 * Nn + gm2 * 2 + head], d2);
            }
        }
    }
}

// ================= fused CSR softmax-aggregation =================
// One warp per (dst node, head); atomic-free single pass.
__global__ void agg_csr_kernel(const int* __restrict__ rowptr, const int* __restrict__ cnt,
                               const int* __restrict__ colidx,
                               const float* __restrict__ h,
                               const float* __restrict__ asad,
                               float* __restrict__ out, int N)
{
    int gw = (blockIdx.x * blockDim.x + threadIdx.x) >> 5;
    int lane = threadIdx.x & 31;
    if (gw >= N * 2) return;
    int node = gw >> 1, head = gw & 1;
    int start = rowptr[node];
    int deg   = cnt[node];
    float adv = asad[2 * N + node * 2 + head];
    const float4* h4 = (const float4*)h + head * 32 + lane;

    float4 acc = make_float4(0.f, 0.f, 0.f, 0.f);
    float den = 0.f;

    int s = __ldg(&colidx[start]);   // deg >= 1 always (self loop)
    for (int i = 0; i < deg; i++) {
        int scur = s;
        if (i + 1 < deg) s = __ldg(&colidx[start + i + 1]);
        float e = __ldg(&asad[scur * 2 + head]) + adv;
        e = e > 0.f ? e : NEG_SLOPE * e;
        float w = __expf(e);
        float4 v = h4[(size_t)scur * 64];
        den += w;
        acc.x = fmaf(w, v.x, acc.x);
        acc.y = fmaf(w, v.y, acc.y);
        acc.z = fmaf(w, v.z, acc.z);
        acc.w = fmaf(w, v.w, acc.w);
    }
    float r = 1.f / (den + EPSV);
    ((float4*)out)[(size_t)node * 64 + head * 32 + lane] =
        make_float4(acc.x * r, acc.y * r, acc.z * r, acc.w * r);
}

// ================= collapsed post-MLP =================
__global__ void wc_kernel(const float* __restrict__ Wp1, const float* __restrict__ bp1,
                          const float* __restrict__ Wp2, const float* __restrict__ bp2,
                          float* __restrict__ wc)
{
    int i = threadIdx.x;  // 256 threads
    float acc = 0.f;
    for (int j = 0; j < DHID; j++) acc += Wp1[i * DHID + j] * Wp2[j];
    wc[i] = acc;
    if (i == 0) {
        float b = 0.f;
        for (int j = 0; j < DHID; j++) b += bp1[j] * Wp2[j];
        wc[DFEAT] = b + bp2[0];
    }
}

__global__ void final_kernel(const float* __restrict__ agg2,
                             const float* __restrict__ b2,
                             const float* __restrict__ wc,
                             float* __restrict__ out, int N)
{
    int gw = (blockIdx.x * blockDim.x + threadIdx.x) >> 5;
    int lane = threadIdx.x & 31;
    if (gw >= N) return;
    const float* hp = agg2 + (size_t)gw * DFEAT;
    float acc = 0.f;
#pragma unroll
    for (int r = 0; r < 2; r++) {
        int cidx = r * 128 + lane * 4;
        float4 v  = *(const float4*)&hp[cidx];
        float4 bb = *(const float4*)&b2[cidx];
        float4 ww = *(const float4*)&wc[cidx];
        acc += fmaxf(v.x + bb.x, 0.f) * ww.x;
        acc += fmaxf(v.y + bb.y, 0.f) * ww.y;
        acc += fmaxf(v.z + bb.z, 0.f) * ww.z;
        acc += fmaxf(v.w + bb.w, 0.f) * ww.w;
    }
#pragma unroll
    for (int o = 16; o; o >>= 1) acc += __shfl_xor_sync(0xffffffffu, acc, o);
    if (lane == 0) {
        float z = acc + wc[DFEAT];
        out[gw] = 1.f / (1.f + expf(-z));
    }
}

// ================= launch =================
extern "C" void kernel_launch(void* const* d_in, const int* in_sizes, int n_in,
                              void* d_out, int out_size)
{
    const float* x      = (const float*)d_in[0];
    const int*   ei     = (const int*)  d_in[1];
    const float* W1     = (const float*)d_in[2];
    const float* a_src1 = (const float*)d_in[3];
    const float* a_dst1 = (const float*)d_in[4];
    const float* b1     = (const float*)d_in[5];
    const float* W2     = (const float*)d_in[6];
    const float* a_src2 = (const float*)d_in[7];
    const float* a_dst2 = (const float*)d_in[8];
    const float* b2     = (const float*)d_in[9];
    const float* Wp1    = (const float*)d_in[10];
    const float* bp1    = (const float*)d_in[11];
    const float* Wp2    = (const float*)d_in[12];
    const float* bp2    = (const float*)d_in[13];

    const int N = in_sizes[0] / 128;
    const int E = in_sizes[1] / 2;
    const int Etot = E + N;

    float *h1, *agg1, *h2, *agg2, *asad, *wc;
    int *cnt, *rowptr, *cursor, *colidx, *bsum;
    cudaGetSymbolAddress((void**)&h1,   g_h1);
    cudaGetSymbolAddress((void**)&agg1, g_agg1);
    cudaGetSymbolAddress((void**)&h2,   g_h2);
    cudaGetSymbolAddress((void**)&agg2, g_agg2);
    cudaGetSymbolAddress((void**)&asad, g_asad);
    cudaGetSymbolAddress((void**)&wc,   g_wc);
    cudaGetSymbolAddress((void**)&cnt,    g_cnt);
    cudaGetSymbolAddress((void**)&rowptr, g_rowptr);
    cudaGetSymbolAddress((void**)&cursor, g_cursor);
    cudaGetSymbolAddress((void**)&colidx, g_colidx);
    cudaGetSymbolAddress((void**)&bsum,   g_bsum);

    const int nb = (N + 255) / 256;
    dim3 gemm_grid((N + 127) / 128, DFEAT / 64);
    const int agg_blocks   = (N * 2 * 32 + 255) / 256;
    const int final_blocks = (N * 32 + 255) / 256;
    const int edge_blocks  = (Etot + 255) / 256;
    const int z2_blocks    = (4 * N + 255) / 256;

    // 1-3: CSR start + zero (asad zeroed for gemm1's fused alpha)
    zero2_kernel<<<z2_blocks, 256>>>(cnt, N, asad, 4 * N);
    count_kernel<<<edge_blocks, 256>>>(ei, cnt, E, Etot);
    scan_block_sums<<<nb, 256>>>(cnt, bsum, N);
    // 4: gemm1 (profile slot)
    gemm_tf32_kernel<0><<<gemm_grid, 256>>>(
        x, W1, nullptr, h1, a_src1, a_dst1, asad, N, DFEAT, 128, N);
    // 5-7: finish CSR
    scan_bsums<<<1, 256>>>(bsum, nb);
    scan_final<<<nb, 256>>>(cnt, bsum, rowptr, cursor, N);
    scatter_kernel<<<edge_blocks, 256>>>(ei, cursor, colidx, E, Etot);
    // 8: layer-1 aggregation
    agg_csr_kernel<<<agg_blocks, 256>>>(rowptr, cnt, colidx, h1, asad, agg1, N);
    // 9-11: layer 2
    zero_f_kernel<<<z2_blocks, 256>>>(asad, 4 * N);
    gemm_tf32_kernel<1><<<gemm_grid, 256>>>(
        agg1, W2, b1, h2, a_src2, a_dst2, asad, N, DFEAT, DFEAT, N);
    agg_csr_kernel<<<agg_blocks, 256>>>(rowptr, cnt, colidx, h2, asad, agg2, N);
    // 12-13: collapsed post-MLP + sigmoid
    wc_kernel<<<1, 256>>>(Wp1, bp1, Wp2, bp2, wc);
    final_kernel<<<final_blocks, 256>>>(agg2, b2, wc, (float*)d_out, N);
}